// round 16
// baseline (speedup 1.0000x reference)
#include <cuda_runtime.h>
#include <math.h>

#define Bv 32
#define Sv 2048
#define Ev 1024
#define Dv 1024

// Scratch (no device allocations)
__device__ float g_pp [Bv * 128];          // hp partials per (batch, itile)
__device__ float g_qp4[4][Bv * Ev];        // q partials: 4 d-chunks
__device__ float g_c  [Bv];
__device__ float g_p  [Bv];
__device__ float g_att[Bv * Sv];
__device__ int   g_qcnt;                   // q/c producers done (self-reset)
__device__ int   g_pass;                   // att blocks past the spin
__device__ int   g_hcnt;                   // hp blocks done (self-reset)

__device__ __forceinline__ float warp_sum(float v) {
#pragma unroll
    for (int o = 16; o > 0; o >>= 1) v += __shfl_xor_sync(0xffffffffu, v, o);
    return v;
}
__device__ __forceinline__ float warp_max(float v) {
#pragma unroll
    for (int o = 16; o > 0; o >>= 1) v = fmaxf(v, __shfl_xor_sync(0xffffffffu, v, o));
    return v;
}

// ---------------------------------------------------------------------------
// k_main: 2336 blocks x 256 threads, ONE node.
//   [0,256)      q partials: (e-tile 128) x (d-chunk 256) x (4 batches)
//   [256,288)    c[b] = h[b]·Wa_b             (q+c signal g_qcnt)
//   [288,1312)   hp partials (8 i x 4 batches) -> g_pp; last finalizes p[b]
//   [1312,2336)  att (single-row loop, ~40 regs): spin g_qcnt==288, 64 s rows.
// All paths naturally <= ~48 regs -> (256,5) binds occupancy, not registers.
// ---------------------------------------------------------------------------
__global__ void __launch_bounds__(256, 5) k_main(const float* __restrict__ enc,
                      const float* __restrict__ vp_b,
                      const float* __restrict__ h,
                      const float* __restrict__ Wa_w,
                      const float* __restrict__ Wa_b,
                      const float* __restrict__ Wp_w,
                      const float* __restrict__ Wp_b,
                      const float* __restrict__ vp_w) {
    __shared__ float4 sbuf[1280];          // 20 KB, aliased by all classes
    int bid = blockIdx.x, t = threadIdx.x;

    if (bid < 256) {
        // ---- q partial path ----
        float*  hs  = (float*)sbuf;        // [4][256] = 4 KB
        float4* red = sbuf + 256;          // [8 dg][4 k][32 col] = 16 KB
        int et = bid & 7;
        int dc = (bid >> 3) & 3;
        int bg = bid >> 5;
        int b0 = bg * 4, d0 = dc * 256, e0 = et * 128;
        for (int idx = t; idx < 4 * 256; idx += 256) {
            int k = idx >> 8, d = idx & 255;
            hs[k * 256 + d] = h[(size_t)(b0 + k) * Dv + d0 + d];
        }
        __syncthreads();
        int col = t & 31, dg = t >> 5;
        float4 acc[4];
#pragma unroll
        for (int k = 0; k < 4; k++) acc[k] = make_float4(0.f, 0.f, 0.f, 0.f);
#pragma unroll 4
        for (int i = 0; i < 32; i++) {
            int d = dg * 32 + i;
            float4 wv = ((const float4*)(Wa_w + (size_t)(d0 + d) * Ev + e0))[col];
#pragma unroll
            for (int k = 0; k < 4; k++) {
                float x = hs[k * 256 + d];
                acc[k].x += wv.x * x; acc[k].y += wv.y * x;
                acc[k].z += wv.z * x; acc[k].w += wv.w * x;
            }
        }
#pragma unroll
        for (int k = 0; k < 4; k++) red[(dg * 4 + k) * 32 + col] = acc[k];
        __syncthreads();
#pragma unroll
        for (int o = 4; o > 0; o >>= 1) {
            if (dg < o) {
#pragma unroll
                for (int k = 0; k < 4; k++) {
                    float4 u = red[(dg * 4 + k) * 32 + col];
                    float4 v = red[((dg + o) * 4 + k) * 32 + col];
                    u.x += v.x; u.y += v.y; u.z += v.z; u.w += v.w;
                    red[(dg * 4 + k) * 32 + col] = u;
                }
            }
            __syncthreads();
        }
        if (dg == 0) {
#pragma unroll
            for (int k = 0; k < 4; k++)
                ((float4*)(g_qp4[dc] + (size_t)(b0 + k) * Ev + e0))[col] =
                    red[k * 32 + col];
        }
        __threadfence();
        __syncthreads();
        if (t == 0) atomicAdd(&g_qcnt, 1);
        return;
    }
    if (bid < 288) {
        // ---- c path ----
        int b = bid - 256;
        float v = 0.f;
        for (int d = t; d < Dv; d += 256) v += h[b * Dv + d] * Wa_b[d];
        v = warp_sum(v);
        __shared__ float redc[8];
        if ((t & 31) == 0) redc[t >> 5] = v;
        __syncthreads();
        if (t == 0) {
            float s = 0.f;
#pragma unroll
            for (int i = 0; i < 8; i++) s += redc[i];
            g_c[b] = s;
            __threadfence();
            atomicAdd(&g_qcnt, 1);
        }
        return;
    }
    if (bid < 1312) {
        // ---- hp path: 8 i per block, 4 batches (lean registers) ----
        float4 (*hs4)[256] = (float4(*)[256])sbuf;   // [4][256] = 16 KB
        __shared__ float wtmp[8][4];
        int id = bid - 288;                // 0..1023
        int b0 = (id >> 7) * 4;            // 8 batch groups of 4
        int itile = id & 127;
        for (int idx = t; idx < 4 * 256; idx += 256) {
            int k = idx >> 8, j = idx & 255;
            hs4[k][j] = ((const float4*)(h + (size_t)(b0 + k) * Dv))[j];
        }
        __syncthreads();
        int w = t >> 5, lane = t & 31;
        int i = itile * 8 + w;
        const float4* wr = (const float4*)(Wp_w + (size_t)i * Dv);
        float acc[4];
#pragma unroll
        for (int k = 0; k < 4; k++) acc[k] = 0.f;
#pragma unroll
        for (int j = lane; j < 256; j += 32) {
            float4 wv = wr[j];
#pragma unroll
            for (int k = 0; k < 4; k++) {
                float4 x = hs4[k][j];
                acc[k] += wv.x * x.x + wv.y * x.y + wv.z * x.z + wv.w * x.w;
            }
        }
#pragma unroll
        for (int k = 0; k < 4; k++) acc[k] = warp_sum(acc[k]);
        if (lane == 0) {
            float bia = Wp_b[i];
            float vp  = vp_w[i];
#pragma unroll
            for (int k = 0; k < 4; k++) wtmp[w][k] = tanhf(acc[k] + bia) * vp;
        }
        __syncthreads();
        if (t < 4) {
            float s = 0.f;
#pragma unroll
            for (int w2 = 0; w2 < 8; w2++) s += wtmp[w2][t];
            g_pp[(b0 + t) * 128 + itile] = s;
        }
        __threadfence();
        __syncthreads();
        __shared__ int hlast;
        if (t == 0) hlast = (atomicAdd(&g_hcnt, 1) == 1023);
        __syncthreads();
        if (hlast) {
            __threadfence();
            int b = t >> 3, part = t & 7;
            float s = 0.f;
#pragma unroll
            for (int j = part; j < 128; j += 8) s += g_pp[b * 128 + j];
#pragma unroll
            for (int o = 4; o > 0; o >>= 1) s += __shfl_xor_sync(0xffffffffu, s, o);
            if (part == 0) {
                float x = s + vp_b[0];
                g_p[b] = (float)Sv / (1.f + expf(-x));
            }
            if (t == 0) g_hcnt = 0;        // reset for next replay
        }
        return;
    }

    // ---- att path: single-row inner loop (R2-proven, ~40 regs) ----
    int id = bid - 1312;
    int tile = id & 31, b = id >> 5;

    if (t == 0) {
        while (*(volatile int*)&g_qcnt < 288) {}
        if (atomicAdd(&g_pass, 1) == 1023) { g_qcnt = 0; g_pass = 0; }
    }
    __syncthreads();
    __threadfence();

    float4* qs = sbuf;                     // 4 KB
    {   // q = sum of 4 d-chunk partials
        float4 s0 = ((const float4*)(g_qp4[0] + b * Ev))[t];
        float4 s1 = ((const float4*)(g_qp4[1] + b * Ev))[t];
        float4 s2 = ((const float4*)(g_qp4[2] + b * Ev))[t];
        float4 s3 = ((const float4*)(g_qp4[3] + b * Ev))[t];
        float4 r;
        r.x = (s0.x + s1.x) + (s2.x + s3.x);
        r.y = (s0.y + s1.y) + (s2.y + s3.y);
        r.z = (s0.z + s1.z) + (s2.z + s3.z);
        r.w = (s0.w + s1.w) + (s2.w + s3.w);
        qs[t] = r;
    }
    __syncthreads();

    int w = t >> 5, lane = t & 31;
    float c = g_c[b];
#pragma unroll
    for (int r = 0; r < 8; r++) {
        int s = tile * 64 + w * 8 + r;
        const float4* er = (const float4*)(enc + ((size_t)b * Sv + s) * Ev);
        float acc = 0.f;
#pragma unroll
        for (int j = lane; j < Ev / 4; j += 32) {
            float4 a = __ldcs(er + j);
            float4 x = qs[j];
            acc += a.x * x.x + a.y * x.y + a.z * x.z + a.w * x.w;
        }
        acc = warp_sum(acc);
        if (lane == 0) g_att[b * Sv + s] = acc + c;
    }
}

// ---------------------------------------------------------------------------
// k_fin: grid (8 e-tiles, 32 batches), 1024 threads. p precomputed -> enc
// window loads issue first and stay in flight under the softmax stats.
// ---------------------------------------------------------------------------
__global__ void k_fin(const float* __restrict__ enc, float* __restrict__ awe,
                      float* __restrict__ alpha) {
    int tile = blockIdx.x, b = blockIdx.y, t = threadIdx.x;
    int lane = t & 31, wrp = t >> 5;
    __shared__ float red[32];
    __shared__ float fin;
    __shared__ float aw[64];
    __shared__ float4 pacc[32][32];        // 16 KB

    float p = g_p[b];
    int lo = (int)floorf(p) - 31;
    if (lo < 0) lo = 0;
    if (lo > Sv - 64) lo = Sv - 64;

    int col = t & 31;
    int rg  = t >> 5;
    const float4* base = (const float4*)(enc + ((size_t)b * Sv + lo) * Ev)
                         + tile * 32;
    float4 v0 = base[(size_t)(rg * 2)     * (Ev / 4) + col];
    float4 v1 = base[(size_t)(rg * 2 + 1) * (Ev / 4) + col];

    float a0 = g_att[b * Sv + t];
    float a1 = g_att[b * Sv + t + 1024];
    float m = warp_max(fmaxf(a0, a1));
    if (lane == 0) red[wrp] = m;
    __syncthreads();
    if (wrp == 0) {
        float v = warp_max(red[lane]);
        if (lane == 0) fin = v;
    }
    __syncthreads();
    float mb = fin;
    float e0 = expf(a0 - mb), e1 = expf(a1 - mb);
    float l = warp_sum(e0 + e1);
    __syncthreads();
    if (lane == 0) red[wrp] = l;
    __syncthreads();
    if (wrp == 0) {
        float v = warp_sum(red[lane]);
        if (lane == 0) fin = v;
    }
    __syncthreads();
    float inv = 1.f / fin;
    float d0 = (float)t - p, d1 = (float)(t + 1024) - p;
    float al0 = e0 * inv * expf(-d0 * d0 * 0.125f);
    float al1 = e1 * inv * expf(-d1 * d1 * 0.125f);
    if (tile == 0) {
        alpha[b * Sv + t]        = al0;
        alpha[b * Sv + t + 1024] = al1;
    }
    int w0 = t - lo, w1 = t + 1024 - lo;
    if ((unsigned)w0 < 64u) aw[w0] = al0;
    if ((unsigned)w1 < 64u) aw[w1] = al1;
    __syncthreads();

    float aA = aw[rg * 2], aB = aw[rg * 2 + 1];
    float4 acc;
    acc.x = v0.x * aA + v1.x * aB;
    acc.y = v0.y * aA + v1.y * aB;
    acc.z = v0.z * aA + v1.z * aB;
    acc.w = v0.w * aA + v1.w * aB;
    pacc[rg][col] = acc;
    __syncthreads();
#pragma unroll
    for (int o = 16; o > 0; o >>= 1) {
        if (rg < o) {
            float4 u = pacc[rg][col], v = pacc[rg + o][col];
            u.x += v.x; u.y += v.y; u.z += v.z; u.w += v.w;
            pacc[rg][col] = u;
        }
        __syncthreads();
    }
    if (t < 32)
        ((float4*)(awe + b * Ev + tile * 128))[t] = pacc[0][t];
}

extern "C" void kernel_launch(void* const* d_in, const int* in_sizes, int n_in,
                              void* d_out, int out_size) {
    const float* enc  = (const float*)d_in[0];   // [B,S,E]
    const float* h    = (const float*)d_in[1];   // [B,D]
    const float* Wa_w = (const float*)d_in[3];   // [D,E]
    const float* Wa_b = (const float*)d_in[4];   // [D]
    const float* Wp_w = (const float*)d_in[5];   // [D,D]
    const float* Wp_b = (const float*)d_in[6];   // [D]
    const float* vp_w = (const float*)d_in[7];   // [1,D]
    const float* vp_b = (const float*)d_in[8];   // [1]

    float* awe   = (float*)d_out;                 // [B,E]
    float* alpha = (float*)d_out + Bv * Ev;       // [B,S]

    k_main<<<2336, 256>>>(enc, vp_b, h, Wa_w, Wa_b, Wp_w, Wp_b, vp_w);
    k_fin <<<dim3(8, Bv), 1024>>>(enc, awe, alpha);
}

// round 17
// speedup vs baseline: 1.1051x; 1.1051x over previous
#include <cuda_runtime.h>
#include <math.h>

#define Bv 32
#define Sv 2048
#define Ev 1024
#define Dv 1024

// Scratch (no device allocations)
__device__ float g_pp [Bv * 128];          // hp partials per (batch, itile)
__device__ float g_qp4[4][Bv * Ev];        // q partials: 4 d-chunks
__device__ float g_c  [Bv];
__device__ float g_p  [Bv];
__device__ float g_att[Bv * Sv];
__device__ int   g_qcnt[8];                // per-batch-group producers done
__device__ int   g_pass[8];                // per-bg att blocks past the spin
__device__ int   g_hcnt;                   // hp blocks done (self-reset)

__device__ __forceinline__ float warp_sum(float v) {
#pragma unroll
    for (int o = 16; o > 0; o >>= 1) v += __shfl_xor_sync(0xffffffffu, v, o);
    return v;
}
__device__ __forceinline__ float warp_max(float v) {
#pragma unroll
    for (int o = 16; o > 0; o >>= 1) v = fmaxf(v, __shfl_xor_sync(0xffffffffu, v, o));
    return v;
}

// ---------------------------------------------------------------------------
// k_main: 1824 blocks x 256 threads, ONE node (R12 structure).
//   [0,256)     q partials: (e-tile 128) x (d-chunk 256) x (4 batches)
//               bids are batch-group-major: bids [bg*32, bg*32+32) serve
//               batches [bg*4, bg*4+4)  -> signal g_qcnt[bg]
//   [256,288)   c[b]                                   -> signal g_qcnt[b>>2]
//   [288,800)   hp partials (8 i x 8 batches) -> g_pp; last finalizes p[b]
//   [800,1824)  att: spin until g_qcnt[bg]==36 (32 q + 4 c for its bg only),
//               then 64 s rows. Early bgs start while later producers run.
// ---------------------------------------------------------------------------
__global__ void __launch_bounds__(256) k_main(const float* __restrict__ enc,
                      const float* __restrict__ vp_b,
                      const float* __restrict__ h,
                      const float* __restrict__ Wa_w,
                      const float* __restrict__ Wa_b,
                      const float* __restrict__ Wp_w,
                      const float* __restrict__ Wp_b,
                      const float* __restrict__ vp_w) {
    __shared__ float4 sbuf[2048];          // 32 KB, aliased by all classes
    int bid = blockIdx.x, t = threadIdx.x;

    if (bid < 256) {
        // ---- q partial path ----
        float*  hs  = (float*)sbuf;        // [4][256] = 4 KB
        float4* red = sbuf + 256;          // [8 dg][4 k][32 col] = 16 KB
        int et = bid & 7;
        int dc = (bid >> 3) & 3;
        int bg = bid >> 5;
        int b0 = bg * 4, d0 = dc * 256, e0 = et * 128;
        for (int idx = t; idx < 4 * 256; idx += 256) {
            int k = idx >> 8, d = idx & 255;
            hs[k * 256 + d] = h[(size_t)(b0 + k) * Dv + d0 + d];
        }
        __syncthreads();
        int col = t & 31, dg = t >> 5;
        float4 acc[4];
#pragma unroll
        for (int k = 0; k < 4; k++) acc[k] = make_float4(0.f, 0.f, 0.f, 0.f);
#pragma unroll 4
        for (int i = 0; i < 32; i++) {
            int d = dg * 32 + i;
            float4 wv = ((const float4*)(Wa_w + (size_t)(d0 + d) * Ev + e0))[col];
#pragma unroll
            for (int k = 0; k < 4; k++) {
                float x = hs[k * 256 + d];
                acc[k].x += wv.x * x; acc[k].y += wv.y * x;
                acc[k].z += wv.z * x; acc[k].w += wv.w * x;
            }
        }
#pragma unroll
        for (int k = 0; k < 4; k++) red[(dg * 4 + k) * 32 + col] = acc[k];
        __syncthreads();
#pragma unroll
        for (int o = 4; o > 0; o >>= 1) {
            if (dg < o) {
#pragma unroll
                for (int k = 0; k < 4; k++) {
                    float4 u = red[(dg * 4 + k) * 32 + col];
                    float4 v = red[((dg + o) * 4 + k) * 32 + col];
                    u.x += v.x; u.y += v.y; u.z += v.z; u.w += v.w;
                    red[(dg * 4 + k) * 32 + col] = u;
                }
            }
            __syncthreads();
        }
        if (dg == 0) {
#pragma unroll
            for (int k = 0; k < 4; k++)
                ((float4*)(g_qp4[dc] + (size_t)(b0 + k) * Ev + e0))[col] =
                    red[k * 32 + col];
        }
        __threadfence();
        __syncthreads();
        if (t == 0) atomicAdd(&g_qcnt[bg], 1);
        return;
    }
    if (bid < 288) {
        // ---- c path ----
        int b = bid - 256;
        float v = 0.f;
        for (int d = t; d < Dv; d += 256) v += h[b * Dv + d] * Wa_b[d];
        v = warp_sum(v);
        __shared__ float redc[8];
        if ((t & 31) == 0) redc[t >> 5] = v;
        __syncthreads();
        if (t == 0) {
            float s = 0.f;
#pragma unroll
            for (int i = 0; i < 8; i++) s += redc[i];
            g_c[b] = s;
            __threadfence();
            atomicAdd(&g_qcnt[b >> 2], 1);
        }
        return;
    }
    if (bid < 800) {
        // ---- hp path: 8 i per block, 8 batches (R12 exact) ----
        float4 (*hs4)[256] = (float4(*)[256])sbuf;   // 32 KB
        __shared__ float wtmp[8][8];
        int id = bid - 288;
        int b0 = (id >> 7) * 8;
        int itile = id & 127;
        for (int idx = t; idx < 8 * 256; idx += 256) {
            int k = idx >> 8, j = idx & 255;
            hs4[k][j] = ((const float4*)(h + (size_t)(b0 + k) * Dv))[j];
        }
        __syncthreads();
        int w = t >> 5, lane = t & 31;
        int i = itile * 8 + w;
        const float4* wr = (const float4*)(Wp_w + (size_t)i * Dv);
        float acc[8];
#pragma unroll
        for (int k = 0; k < 8; k++) acc[k] = 0.f;
#pragma unroll
        for (int j = lane; j < 256; j += 32) {
            float4 wv = wr[j];
#pragma unroll
            for (int k = 0; k < 8; k++) {
                float4 x = hs4[k][j];
                acc[k] += wv.x * x.x + wv.y * x.y + wv.z * x.z + wv.w * x.w;
            }
        }
#pragma unroll
        for (int k = 0; k < 8; k++) acc[k] = warp_sum(acc[k]);
        if (lane == 0) {
            float bia = Wp_b[i];
            float vp  = vp_w[i];
#pragma unroll
            for (int k = 0; k < 8; k++) wtmp[w][k] = tanhf(acc[k] + bia) * vp;
        }
        __syncthreads();
        if (t < 8) {
            float s = 0.f;
#pragma unroll
            for (int w2 = 0; w2 < 8; w2++) s += wtmp[w2][t];
            g_pp[(b0 + t) * 128 + itile] = s;
        }
        __threadfence();
        __syncthreads();
        __shared__ int hlast;
        if (t == 0) hlast = (atomicAdd(&g_hcnt, 1) == 511);
        __syncthreads();
        if (hlast) {
            __threadfence();
            int b = t >> 3, part = t & 7;
            float s = 0.f;
#pragma unroll
            for (int j = part; j < 128; j += 8) s += g_pp[b * 128 + j];
#pragma unroll
            for (int o = 4; o > 0; o >>= 1) s += __shfl_xor_sync(0xffffffffu, s, o);
            if (part == 0) {
                float x = s + vp_b[0];
                g_p[b] = (float)Sv / (1.f + expf(-x));
            }
            if (t == 0) g_hcnt = 0;        // reset for next replay
        }
        return;
    }

    // ---- att path (R12 exact, per-bg gating) ----
    int id = bid - 800;
    int tile = id & 31, b = id >> 5;
    int bg = b >> 2;

    if (t == 0) {
        while (*(volatile int*)&g_qcnt[bg] < 36) {}
        // 128 att blocks per bg (32 tiles x 4 batches); last resets
        if (atomicAdd(&g_pass[bg], 1) == 127) { g_qcnt[bg] = 0; g_pass[bg] = 0; }
    }
    __syncthreads();
    __threadfence();

    float4* qs = sbuf;                     // 4 KB
    {   // q = sum of 4 d-chunk partials
        float4 s0 = ((const float4*)(g_qp4[0] + b * Ev))[t];
        float4 s1 = ((const float4*)(g_qp4[1] + b * Ev))[t];
        float4 s2 = ((const float4*)(g_qp4[2] + b * Ev))[t];
        float4 s3 = ((const float4*)(g_qp4[3] + b * Ev))[t];
        float4 r;
        r.x = (s0.x + s1.x) + (s2.x + s3.x);
        r.y = (s0.y + s1.y) + (s2.y + s3.y);
        r.z = (s0.z + s1.z) + (s2.z + s3.z);
        r.w = (s0.w + s1.w) + (s2.w + s3.w);
        qs[t] = r;
    }
    __syncthreads();

    int w = t >> 5, lane = t & 31;
    float c = g_c[b];
#pragma unroll
    for (int r = 0; r < 8; r += 2) {
        int s = tile * 64 + w * 8 + r;
        const float4* er0 = (const float4*)(enc + ((size_t)b * Sv + s)     * Ev);
        const float4* er1 = (const float4*)(enc + ((size_t)b * Sv + s + 1) * Ev);
        float acc0 = 0.f, acc1 = 0.f;
#pragma unroll
        for (int j = lane; j < Ev / 4; j += 32) {
            float4 x  = qs[j];
            float4 a0 = __ldcs(er0 + j);
            float4 a1 = __ldcs(er1 + j);
            acc0 += a0.x * x.x + a0.y * x.y + a0.z * x.z + a0.w * x.w;
            acc1 += a1.x * x.x + a1.y * x.y + a1.z * x.z + a1.w * x.w;
        }
        acc0 = warp_sum(acc0);
        acc1 = warp_sum(acc1);
        if (lane == 0) {
            g_att[b * Sv + s]     = acc0 + c;
            g_att[b * Sv + s + 1] = acc1 + c;
        }
    }
}

// ---------------------------------------------------------------------------
// k_fin: grid (8 e-tiles, 32 batches), 1024 threads. p precomputed -> enc
// window loads issue first and stay in flight under the softmax stats.
// ---------------------------------------------------------------------------
__global__ void k_fin(const float* __restrict__ enc, float* __restrict__ awe,
                      float* __restrict__ alpha) {
    int tile = blockIdx.x, b = blockIdx.y, t = threadIdx.x;
    int lane = t & 31, wrp = t >> 5;
    __shared__ float red[32];
    __shared__ float fin;
    __shared__ float aw[64];
    __shared__ float4 pacc[32][32];        // 16 KB

    float p = g_p[b];
    int lo = (int)floorf(p) - 31;
    if (lo < 0) lo = 0;
    if (lo > Sv - 64) lo = Sv - 64;

    int col = t & 31;
    int rg  = t >> 5;
    const float4* base = (const float4*)(enc + ((size_t)b * Sv + lo) * Ev)
                         + tile * 32;
    float4 v0 = base[(size_t)(rg * 2)     * (Ev / 4) + col];
    float4 v1 = base[(size_t)(rg * 2 + 1) * (Ev / 4) + col];

    float a0 = g_att[b * Sv + t];
    float a1 = g_att[b * Sv + t + 1024];
    float m = warp_max(fmaxf(a0, a1));
    if (lane == 0) red[wrp] = m;
    __syncthreads();
    if (wrp == 0) {
        float v = warp_max(red[lane]);
        if (lane == 0) fin = v;
    }
    __syncthreads();
    float mb = fin;
    float e0 = expf(a0 - mb), e1 = expf(a1 - mb);
    float l = warp_sum(e0 + e1);
    __syncthreads();
    if (lane == 0) red[wrp] = l;
    __syncthreads();
    if (wrp == 0) {
        float v = warp_sum(red[lane]);
        if (lane == 0) fin = v;
    }
    __syncthreads();
    float inv = 1.f / fin;
    float d0 = (float)t - p, d1 = (float)(t + 1024) - p;
    float al0 = e0 * inv * expf(-d0 * d0 * 0.125f);
    float al1 = e1 * inv * expf(-d1 * d1 * 0.125f);
    if (tile == 0) {
        alpha[b * Sv + t]        = al0;
        alpha[b * Sv + t + 1024] = al1;
    }
    int w0 = t - lo, w1 = t + 1024 - lo;
    if ((unsigned)w0 < 64u) aw[w0] = al0;
    if ((unsigned)w1 < 64u) aw[w1] = al1;
    __syncthreads();

    float aA = aw[rg * 2], aB = aw[rg * 2 + 1];
    float4 acc;
    acc.x = v0.x * aA + v1.x * aB;
    acc.y = v0.y * aA + v1.y * aB;
    acc.z = v0.z * aA + v1.z * aB;
    acc.w = v0.w * aA + v1.w * aB;
    pacc[rg][col] = acc;
    __syncthreads();
#pragma unroll
    for (int o = 16; o > 0; o >>= 1) {
        if (rg < o) {
            float4 u = pacc[rg][col], v = pacc[rg + o][col];
            u.x += v.x; u.y += v.y; u.z += v.z; u.w += v.w;
            pacc[rg][col] = u;
        }
        __syncthreads();
    }
    if (t < 32)
        ((float4*)(awe + b * Ev + tile * 128))[t] = pacc[0][t];
}

extern "C" void kernel_launch(void* const* d_in, const int* in_sizes, int n_in,
                              void* d_out, int out_size) {
    const float* enc  = (const float*)d_in[0];   // [B,S,E]
    const float* h    = (const float*)d_in[1];   // [B,D]
    const float* Wa_w = (const float*)d_in[3];   // [D,E]
    const float* Wa_b = (const float*)d_in[4];   // [D]
    const float* Wp_w = (const float*)d_in[5];   // [D,D]
    const float* Wp_b = (const float*)d_in[6];   // [D]
    const float* vp_w = (const float*)d_in[7];   // [1,D]
    const float* vp_b = (const float*)d_in[8];   // [1]

    float* awe   = (float*)d_out;                 // [B,E]
    float* alpha = (float*)d_out + Bv * Ev;       // [B,S]

    k_main<<<1824, 256>>>(enc, vp_b, h, Wa_w, Wa_b, Wp_w, Wp_b, vp_w);
    k_fin <<<dim3(8, Bv), 1024>>>(enc, awe, alpha);
}